// round 11
// baseline (speedup 1.0000x reference)
#include <cuda_runtime.h>

#define N_NODES 4096
#define T_STEPS 48
#define IN_DIM  2
#define H_DIM   64
#define H4      256
#define P_DIM   12
#define MAXW    256
#define NB      128      // persistent blocks (<=148 SMs -> all co-resident)
#define SR      34       // padded smem row stride

typedef unsigned long long ull;

// ---------------- device scratch (static, allocation-free) ----------------
__device__ float g_dinv[N_NODES];
__device__ int   g_nnz[N_NODES];
__device__ int   g_cols[N_NODES * MAXW];
__device__ float g_vals[N_NODES * MAXW];
__device__ float g_h0[2][N_NODES * H_DIM];
__device__ float g_h1[2][N_NODES * H_DIM];
__device__ float g_Wg0[66 * H4];
__device__ float g_Wl0[66 * H4];
__device__ float g_b0[H4];
__device__ float g_Wg1[128 * H4];
__device__ float g_Wl1[128 * H4];
__device__ float g_b1[H4];
__device__ unsigned g_barArr;
__device__ unsigned g_barGen;

// ---------------- packed fp32x2 helpers ----------------
__device__ __forceinline__ ull pack2(float a, float b) {
    ull r; asm("mov.b64 %0, {%1, %2};" : "=l"(r) : "f"(a), "f"(b)); return r;
}
__device__ __forceinline__ void unpack2(ull v, float& lo, float& hi) {
    asm("mov.b64 {%0, %1}, %2;" : "=f"(lo), "=f"(hi) : "l"(v));
}
__device__ __forceinline__ void fma2(ull& d, ull a, ull b) {
    asm("fma.rn.f32x2 %0, %1, %2, %0;" : "+l"(d) : "l"(a), "l"(b));
}
__device__ __forceinline__ float sigmoidf_(float x) {
    return 1.0f / (1.0f + __expf(-x));
}

// ---------------- grid barrier (threadfence-reduction pattern) -----------
__device__ __forceinline__ void gridbar() {
    __syncthreads();
    if (threadIdx.x == 0) {
        unsigned gen = *(volatile unsigned*)&g_barGen;
        __threadfence();
        unsigned prev = atomicAdd(&g_barArr, 1u);
        if (prev == NB - 1) {
            g_barArr = 0;
            __threadfence();
            atomicExch(&g_barGen, gen + 1u);
        } else {
            while (*(volatile unsigned*)&g_barGen == gen) { }
            __threadfence();
        }
    }
    __syncthreads();
}

// ---------------- preprocessing ----------------
__global__ void rowsum_kernel(const float* __restrict__ adj) {
    int i = blockIdx.x;
    const float* row = adj + (size_t)i * N_NODES;
    float s = 0.f;
    for (int j = threadIdx.x; j < N_NODES; j += 256) s += row[j];
    #pragma unroll
    for (int o = 16; o > 0; o >>= 1) s += __shfl_xor_sync(0xffffffffu, s, o);
    __shared__ float red[8];
    if ((threadIdx.x & 31) == 0) red[threadIdx.x >> 5] = s;
    __syncthreads();
    if (threadIdx.x == 0) {
        float t = 0.f;
        for (int w = 0; w < 8; w++) t += red[w];
        g_dinv[i] = rsqrtf(t + 1.0f);
    }
}

// deterministic padded-CSR build (block prefix scan, no atomics)
__global__ void build_sparse(const float* __restrict__ adj) {
    int i = blockIdx.x;
    int tid = threadIdx.x;  // 256
    __shared__ int sc[256];
    int   locj[16];
    float locv[16];
    int lc = 0;
    int jbase = tid * 16;
    const float* row = adj + (size_t)i * N_NODES;
    #pragma unroll
    for (int jj = 0; jj < 16; jj++) {
        int j = jbase + jj;
        float a = row[j];
        bool dg = (j == i);
        if (a != 0.f || dg) { locj[lc] = j; locv[lc] = a + (dg ? 1.f : 0.f); lc++; }
    }
    sc[tid] = lc;
    __syncthreads();
    for (int off = 1; off < 256; off <<= 1) {
        int v = (tid >= off) ? sc[tid - off] : 0;
        __syncthreads();
        sc[tid] += v;
        __syncthreads();
    }
    int start = sc[tid] - lc;
    float di = g_dinv[i];
    for (int u = 0; u < lc; u++) {
        int p = start + u;
        if (p < MAXW) {
            int j = locj[u];
            g_cols[i * MAXW + p] = j;
            g_vals[i * MAXW + p] = locv[u] * di * g_dinv[j];
        }
    }
    if (tid == 255) g_nnz[i] = min(sc[255], MAXW);
}

__global__ void prep_weights(
    const float* __restrict__ gcWi0, const float* __restrict__ gcbi0,
    const float* __restrict__ gcWh0, const float* __restrict__ gcbh0,
    const float* __restrict__ liWi0, const float* __restrict__ libi0,
    const float* __restrict__ liWh0, const float* __restrict__ libh0,
    const float* __restrict__ gcWi1, const float* __restrict__ gcbi1,
    const float* __restrict__ gcWh1, const float* __restrict__ gcbh1,
    const float* __restrict__ liWi1, const float* __restrict__ libi1,
    const float* __restrict__ liWh1, const float* __restrict__ libh1) {
    int c = threadIdx.x;  // 256 threads, 1 block
    for (int r = 0; r < 2;  r++) g_Wg0[r * H4 + c]        = gcWi0[r * H4 + c];
    for (int r = 0; r < 64; r++) g_Wg0[(r + 2) * H4 + c]  = gcWh0[r * H4 + c];
    for (int r = 0; r < 2;  r++) g_Wl0[r * H4 + c]        = liWi0[r * H4 + c];
    for (int r = 0; r < 64; r++) g_Wl0[(r + 2) * H4 + c]  = liWh0[r * H4 + c];
    for (int r = 0; r < 64; r++) g_Wg1[r * H4 + c]        = gcWi1[r * H4 + c];
    for (int r = 0; r < 64; r++) g_Wg1[(r + 64) * H4 + c] = gcWh1[r * H4 + c];
    for (int r = 0; r < 64; r++) g_Wl1[r * H4 + c]        = liWi1[r * H4 + c];
    for (int r = 0; r < 64; r++) g_Wl1[(r + 64) * H4 + c] = liWh1[r * H4 + c];
    g_b0[c] = gcbi0[c] + gcbh0[c] + libi0[c] + libh0[c];
    g_b1[c] = gcbi1[c] + gcbh1[c] + libi1[c] + libh1[c];
}

__global__ void init_state() {
    int idx = blockIdx.x * blockDim.x + threadIdx.x;
    int tot = N_NODES * H_DIM;
    if (idx < tot) {
        g_h0[0][idx] = 0.f; g_h0[1][idx] = 0.f;
        g_h1[0][idx] = 0.f; g_h1[1][idx] = 0.f;
    }
    if (idx == 0) { g_barArr = 0u; g_barGen = 0u; }
}

// ---------------- persistent kernel phases ----------------

// SpMM for this block's 32 rows -> s_az (transposed [k][r]).
// L==0: az = [A@x (k=0,1) | A@h0cur (k=2..65)]
// L==1: az = [A@h0nxt (k=0..63) | A@h1cur (k=64..127)]
template <int L>
__device__ __forceinline__ void spmm_phase(
    const float* __restrict__ x_t, const float* __restrict__ hA,
    const float* __restrict__ hB,
    float* s_az, int* s_ecol, float* s_eval,
    int row0, int w, int lane) {
    int* ec = s_ecol + w * MAXW;
    float* ev = s_eval + w * MAXW;
    for (int rr = 0; rr < 4; rr++) {
        int r = 4 * w + rr;
        int i = row0 + r;
        int nnz = g_nnz[i];
        const int*   cp = g_cols + (size_t)i * MAXW;
        const float* vp = g_vals + (size_t)i * MAXW;
        for (int e = lane; e < nnz; e += 32) { ec[e] = cp[e]; ev[e] = vp[e]; }
        __syncwarp();
        float a0 = 0.f, a1 = 0.f, b0 = 0.f, b1 = 0.f;
        int e = 0;
        for (; e + 8 <= nnz; e += 8) {
            float2 hv[8], xv[8]; float vv[8];
            #pragma unroll
            for (int u = 0; u < 8; u++) {
                int j = ec[e + u];
                vv[u] = ev[e + u];
                hv[u] = *(const float2*)(hA + (size_t)j * H_DIM + 2 * lane);
                if (L == 0) xv[u] = *(const float2*)(x_t + (size_t)j * IN_DIM);
                else        xv[u] = *(const float2*)(hB + (size_t)j * H_DIM + 2 * lane);
            }
            #pragma unroll
            for (int u = 0; u < 8; u++) {
                a0 += vv[u] * hv[u].x; a1 += vv[u] * hv[u].y;
                b0 += vv[u] * xv[u].x; b1 += vv[u] * xv[u].y;
            }
        }
        for (; e < nnz; e++) {
            int j = ec[e]; float v = ev[e];
            float2 hv = *(const float2*)(hA + (size_t)j * H_DIM + 2 * lane);
            a0 += v * hv.x; a1 += v * hv.y;
            if (L == 0) {
                float2 xv = *(const float2*)(x_t + (size_t)j * IN_DIM);
                b0 += v * xv.x; b1 += v * xv.y;
            } else {
                float2 xv = *(const float2*)(hB + (size_t)j * H_DIM + 2 * lane);
                b0 += v * xv.x; b1 += v * xv.y;
            }
        }
        if (L == 0) {
            s_az[(2 + 2 * lane) * SR + r] = a0;
            s_az[(3 + 2 * lane) * SR + r] = a1;
            if (lane == 0) { s_az[0 * SR + r] = b0; s_az[1 * SR + r] = b1; }
        } else {
            s_az[(2 * lane) * SR + r]      = a0;
            s_az[(2 * lane + 1) * SR + r]  = a1;
            s_az[(64 + 2 * lane) * SR + r] = b0;
            s_az[(65 + 2 * lane) * SR + r] = b1;
        }
        __syncwarp();
    }
}

// Stage own-row z tiles: L0: [x | h0cur], L1: [h0nxt | h1cur]
template <int L>
__device__ __forceinline__ void stage_z(
    const float* __restrict__ x_t, const float* __restrict__ zA,
    const float* __restrict__ zB, float* s_z, int row0, int tid) {
    constexpr int K = L ? 128 : 66;
    for (int idx = tid; idx < 32 * K; idx += 256) {
        int r = idx / K, k = idx - r * K;
        int i = row0 + r;
        float v;
        if (L == 0) v = (k < 2)  ? x_t[(size_t)i * IN_DIM + k] : zA[(size_t)i * H_DIM + (k - 2)];
        else        v = (k < 64) ? zA[(size_t)i * H_DIM + k]   : zB[(size_t)i * H_DIM + (k - 64)];
        s_z[k * SR + r] = v;
    }
}

// Dense GEMM (az@Wg + z@Wl + b) + gates + state update for 32 rows.
template <int L>
__device__ __forceinline__ void cell_phase(
    float* s_az, float* s_z, float* s_comb, float* s_c,
    float* __restrict__ h_out, int row0, int tid) {
    constexpr int K = L ? 128 : 66;
    const float* Wg   = L ? g_Wg1 : g_Wg0;
    const float* Wl   = L ? g_Wl1 : g_Wl0;
    const float* bias = L ? g_b1  : g_b0;

    int half = tid >> 7;       // 0/1 -> rows 16*half .. +15
    int t    = tid & 127;
    int c0 = t, c1 = t + 128;
    int pbase = 8 * half;      // ull index offset into row-pair arrays

    ull accA[8], accB[8];
    const ull zz = pack2(0.f, 0.f);
    #pragma unroll
    for (int rp = 0; rp < 8; rp++) { accA[rp] = zz; accB[rp] = zz; }

    #pragma unroll 2
    for (int k = 0; k < K; k++) {
        float wgA = __ldg(&Wg[k * H4 + c0]);
        float wgB = __ldg(&Wg[k * H4 + c1]);
        float wlA = __ldg(&Wl[k * H4 + c0]);
        float wlB = __ldg(&Wl[k * H4 + c1]);
        ull wgAp = pack2(wgA, wgA), wgBp = pack2(wgB, wgB);
        ull wlAp = pack2(wlA, wlA), wlBp = pack2(wlB, wlB);
        const ull* a2 = reinterpret_cast<const ull*>(s_az + k * SR) + pbase;
        const ull* b2 = reinterpret_cast<const ull*>(s_z  + k * SR) + pbase;
        #pragma unroll
        for (int rp = 0; rp < 8; rp++) {
            ull av = a2[rp];
            fma2(accA[rp], av, wgAp);
            fma2(accB[rp], av, wgBp);
        }
        #pragma unroll
        for (int rp = 0; rp < 8; rp++) {
            ull bv = b2[rp];
            fma2(accA[rp], bv, wlAp);
            fma2(accB[rp], bv, wlBp);
        }
    }
    __syncthreads();  // done reading s_az/s_z; comb aliases them

    float bA = bias[c0], bB = bias[c1];
    #pragma unroll
    for (int rp = 0; rp < 8; rp++) {
        int r = 16 * half + 2 * rp;
        float lo, hi;
        unpack2(accA[rp], lo, hi);
        s_comb[r * H4 + c0]       = lo + bA;
        s_comb[(r + 1) * H4 + c0] = hi + bA;
        unpack2(accB[rp], lo, hi);
        s_comb[r * H4 + c1]       = lo + bB;
        s_comb[(r + 1) * H4 + c1] = hi + bB;
    }
    __syncthreads();

    float* cl = s_c + L * (32 * H_DIM);
    for (int u = tid; u < 32 * H_DIM; u += 256) {
        int r = u >> 6, hc = u & 63;
        const float* cb = s_comb + r * H4;
        float ig = cb[hc];
        float fg = cb[64 + hc];
        float og = cb[128 + hc];
        float gg = cb[192 + hc];
        float cold = cl[u];
        float nc = sigmoidf_(fg) * cold + sigmoidf_(ig) * tanhf(gg);
        float nh = sigmoidf_(og) * tanhf(nc);
        cl[u] = nc;
        h_out[(size_t)(row0 + r) * H_DIM + hc] = nh;
    }
}

// ---------------- the persistent kernel ----------------
// smem layout (floats):
//   [0, 4352)        s_az  (128 x 34)           \ aliased by s_comb (32x256=8192)
//   [4352, 8704)     s_z   (128 x 34)           /
//   [8704, 10752)    s_ecol (8 warps x 256 ints)
//   [10752, 12800)   s_eval
//   [12800, 16896)   s_c   (2 layers x 32 x 64)  persistent across steps
#define SMEM_FLOATS 16896
#define SMEM_BYTES  (SMEM_FLOATS * 4)

__global__ void __launch_bounds__(256, 1) persist_kernel(
    const float* __restrict__ x,
    const float* __restrict__ outW,
    const float* __restrict__ outb,
    float* __restrict__ out) {
    extern __shared__ __align__(16) float sm[];
    float* s_az   = sm;
    float* s_z    = sm + 4352;
    float* s_comb = sm;                       // alias az+z
    int*   s_ecol = (int*)(sm + 8704);
    float* s_eval = sm + 10752;
    float* s_c    = sm + 12800;

    int tid  = threadIdx.x;
    int w    = tid >> 5, lane = tid & 31;
    int row0 = blockIdx.x * 32;

    for (int u = tid; u < 2 * 32 * H_DIM; u += 256) s_c[u] = 0.f;
    __syncthreads();

    int cur = 0;
    for (int t = 0; t < T_STEPS; t++) {
        const float* x_t = x + (size_t)t * N_NODES * IN_DIM;
        const float* h0c = g_h0[cur];
        float*       h0n = g_h0[cur ^ 1];
        const float* h1c = g_h1[cur];
        float*       h1n = g_h1[cur ^ 1];

        // ---- layer 0 ----
        spmm_phase<0>(x_t, h0c, nullptr, s_az, s_ecol, s_eval, row0, w, lane);
        stage_z<0>(x_t, h0c, nullptr, s_z, row0, tid);
        __syncthreads();
        cell_phase<0>(s_az, s_z, s_comb, s_c, h0n, row0, tid);
        gridbar();

        // ---- layer 1 ----
        spmm_phase<1>(nullptr, h0n, h1c, s_az, s_ecol, s_eval, row0, w, lane);
        stage_z<1>(nullptr, h0n, h1c, s_z, row0, tid);
        __syncthreads();
        cell_phase<1>(s_az, s_z, s_comb, s_c, h1n, row0, tid);
        gridbar();

        cur ^= 1;
    }

    // ---- output: out = h1 @ outW + outb for own 32 rows ----
    const float* hf = g_h1[cur];
    for (int u = tid; u < 32 * P_DIM; u += 256) {
        int r = u / P_DIM, p = u - r * P_DIM;
        int i = row0 + r;
        float acc = outb[p];
        const float* hr = hf + (size_t)i * H_DIM;
        #pragma unroll
        for (int c2 = 0; c2 < H_DIM; c2++) acc += hr[c2] * __ldg(&outW[c2 * P_DIM + p]);
        out[(size_t)i * P_DIM + p] = acc;
    }
}

// ---------------- launch ----------------
extern "C" void kernel_launch(void* const* d_in, const int* in_sizes, int n_in,
                              void* d_out, int out_size) {
    const float* x     = (const float*)d_in[0];
    const float* adj   = (const float*)d_in[1];
    const float* gcWi0 = (const float*)d_in[2];
    const float* gcbi0 = (const float*)d_in[3];
    const float* gcWh0 = (const float*)d_in[4];
    const float* gcbh0 = (const float*)d_in[5];
    const float* liWi0 = (const float*)d_in[6];
    const float* libi0 = (const float*)d_in[7];
    const float* liWh0 = (const float*)d_in[8];
    const float* libh0 = (const float*)d_in[9];
    const float* gcWi1 = (const float*)d_in[10];
    const float* gcbi1 = (const float*)d_in[11];
    const float* gcWh1 = (const float*)d_in[12];
    const float* gcbh1 = (const float*)d_in[13];
    const float* liWi1 = (const float*)d_in[14];
    const float* libi1 = (const float*)d_in[15];
    const float* liWh1 = (const float*)d_in[16];
    const float* libh1 = (const float*)d_in[17];
    const float* outW  = (const float*)d_in[18];
    const float* outb  = (const float*)d_in[19];

    static int smem_set = 0;
    if (!smem_set) {
        cudaFuncSetAttribute(persist_kernel,
                             cudaFuncAttributeMaxDynamicSharedMemorySize,
                             SMEM_BYTES);
        smem_set = 1;
    }

    rowsum_kernel<<<N_NODES, 256>>>(adj);
    build_sparse<<<N_NODES, 256>>>(adj);
    prep_weights<<<1, 256>>>(gcWi0, gcbi0, gcWh0, gcbh0, liWi0, libi0, liWh0, libh0,
                             gcWi1, gcbi1, gcWh1, gcbh1, liWi1, libi1, liWh1, libh1);
    init_state<<<(N_NODES * H_DIM + 255) / 256, 256>>>();
    persist_kernel<<<NB, 256, SMEM_BYTES>>>(x, outW, outb, (float*)d_out);
}

// round 13
// speedup vs baseline: 2.2552x; 2.2552x over previous
#include <cuda_runtime.h>

#define N_NODES 4096
#define T_STEPS 48
#define IN_DIM  2
#define H_DIM   64
#define H4      256
#define P_DIM   12
#define MAXW    160      // max nnz/row (mean ~42, >18 sigma margin)
#define NBW     128      // worker blocks (32 rows each)
#define NBT     148      // total blocks incl. barrier spinners (full grid)
#define SR      34       // padded smem row stride (floats)

typedef unsigned long long ull;

// ---------------- device scratch (static, allocation-free) ----------------
__device__ float g_dinv[N_NODES];
__device__ int   g_nnz[N_NODES];
__device__ int   g_cols[N_NODES * MAXW];
__device__ float g_vals[N_NODES * MAXW];
__device__ float g_h0[2][N_NODES * H_DIM];
__device__ float g_h1[2][N_NODES * H_DIM];
__device__ float g_xT[N_NODES * T_STEPS * IN_DIM];   // [j][t][k]
__device__ float g_AX[T_STEPS * N_NODES * IN_DIM];   // [t][i][k]
__device__ float g_Wg0[66 * H4];
__device__ float g_Wl0[66 * H4];
__device__ float g_b0[H4];
__device__ float g_Wg1[128 * H4];
__device__ float g_Wl1[128 * H4];
__device__ float g_b1[H4];
__device__ unsigned g_cnt;
__device__ volatile unsigned g_gen;

// ---------------- packed fp32x2 helpers ----------------
__device__ __forceinline__ ull pack2(float a, float b) {
    ull r; asm("mov.b64 %0, {%1, %2};" : "=l"(r) : "f"(a), "f"(b)); return r;
}
__device__ __forceinline__ void unpack2(ull v, float& lo, float& hi) {
    asm("mov.b64 {%0, %1}, %2;" : "=f"(lo), "=f"(hi) : "l"(v));
}
__device__ __forceinline__ void fma2(ull& d, ull a, ull b) {
    asm("fma.rn.f32x2 %0, %1, %2, %0;" : "+l"(d) : "l"(a), "l"(b));
}
__device__ __forceinline__ float sigmoidf_(float x) {
    return 1.0f / (1.0f + __expf(-x));
}

// ---------------- grid barrier (generation counter, 148 arrivals) --------
__device__ __forceinline__ void gridbar() {
    __threadfence();
    __syncthreads();
    if (threadIdx.x == 0) {
        unsigned g = g_gen;
        if (atomicAdd(&g_cnt, 1u) == NBT - 1) {
            g_cnt = 0u;
            __threadfence();
            g_gen = g + 1u;
        } else {
            while (g_gen == g) __nanosleep(64);
        }
        __threadfence();
    }
    __syncthreads();
}

// ---------------- preprocessing ----------------
__global__ void rowsum_kernel(const float* __restrict__ adj) {
    int i = blockIdx.x;
    const float* row = adj + (size_t)i * N_NODES;
    float s = 0.f;
    for (int j = threadIdx.x; j < N_NODES; j += 256) s += row[j];
    #pragma unroll
    for (int o = 16; o > 0; o >>= 1) s += __shfl_xor_sync(0xffffffffu, s, o);
    __shared__ float red[8];
    if ((threadIdx.x & 31) == 0) red[threadIdx.x >> 5] = s;
    __syncthreads();
    if (threadIdx.x == 0) {
        float t = 0.f;
        for (int w = 0; w < 8; w++) t += red[w];
        g_dinv[i] = rsqrtf(t + 1.0f);
    }
}

// deterministic padded-CSR build (block prefix scan, no atomics)
__global__ void build_sparse(const float* __restrict__ adj) {
    int i = blockIdx.x;
    int tid = threadIdx.x;  // 256
    __shared__ int sc[256];
    int   locj[16];
    float locv[16];
    int lc = 0;
    int jbase = tid * 16;
    const float* row = adj + (size_t)i * N_NODES;
    #pragma unroll
    for (int jj = 0; jj < 16; jj++) {
        int j = jbase + jj;
        float a = row[j];
        bool dg = (j == i);
        if (a != 0.f || dg) { locj[lc] = j; locv[lc] = a + (dg ? 1.f : 0.f); lc++; }
    }
    sc[tid] = lc;
    __syncthreads();
    for (int off = 1; off < 256; off <<= 1) {
        int v = (tid >= off) ? sc[tid - off] : 0;
        __syncthreads();
        sc[tid] += v;
        __syncthreads();
    }
    int start = sc[tid] - lc;
    float di = g_dinv[i];
    for (int u = 0; u < lc; u++) {
        int p = start + u;
        if (p < MAXW) {
            int j = locj[u];
            g_cols[i * MAXW + p] = j;
            g_vals[i * MAXW + p] = locv[u] * di * g_dinv[j];
        }
    }
    if (tid == 255) g_nnz[i] = min(sc[255], MAXW);
}

__global__ void prep_weights(
    const float* __restrict__ gcWi0, const float* __restrict__ gcbi0,
    const float* __restrict__ gcWh0, const float* __restrict__ gcbh0,
    const float* __restrict__ liWi0, const float* __restrict__ libi0,
    const float* __restrict__ liWh0, const float* __restrict__ libh0,
    const float* __restrict__ gcWi1, const float* __restrict__ gcbi1,
    const float* __restrict__ gcWh1, const float* __restrict__ gcbh1,
    const float* __restrict__ liWi1, const float* __restrict__ libi1,
    const float* __restrict__ liWh1, const float* __restrict__ libh1) {
    int c = threadIdx.x;  // 256 threads, 1 block
    for (int r = 0; r < 2;  r++) g_Wg0[r * H4 + c]        = gcWi0[r * H4 + c];
    for (int r = 0; r < 64; r++) g_Wg0[(r + 2) * H4 + c]  = gcWh0[r * H4 + c];
    for (int r = 0; r < 2;  r++) g_Wl0[r * H4 + c]        = liWi0[r * H4 + c];
    for (int r = 0; r < 64; r++) g_Wl0[(r + 2) * H4 + c]  = liWh0[r * H4 + c];
    for (int r = 0; r < 64; r++) g_Wg1[r * H4 + c]        = gcWi1[r * H4 + c];
    for (int r = 0; r < 64; r++) g_Wg1[(r + 64) * H4 + c] = gcWh1[r * H4 + c];
    for (int r = 0; r < 64; r++) g_Wl1[r * H4 + c]        = liWi1[r * H4 + c];
    for (int r = 0; r < 64; r++) g_Wl1[(r + 64) * H4 + c] = liWh1[r * H4 + c];
    g_b0[c] = gcbi0[c] + gcbh0[c] + libi0[c] + libh0[c];
    g_b1[c] = gcbi1[c] + gcbh1[c] + libi1[c] + libh1[c];
}

// x[t][j][k] -> xT[j][t][k]  (1.6 MB, trivial)
__global__ void xpose_kernel(const float* __restrict__ x) {
    int idx = blockIdx.x * 256 + threadIdx.x;
    if (idx < T_STEPS * N_NODES * IN_DIM) {
        int t = idx / (N_NODES * IN_DIM);
        int rem = idx - t * (N_NODES * IN_DIM);
        int j = rem >> 1, k = rem & 1;
        g_xT[j * (T_STEPS * IN_DIM) + t * IN_DIM + k] = x[idx];
    }
}

// AX[t][i][k] = sum_e v * xT[j][t][k]  (block per row, 96 active threads)
__global__ void __launch_bounds__(128) ax_kernel() {
    __shared__ int   ec[MAXW];
    __shared__ float ev[MAXW];
    int i = blockIdx.x;
    int tid = threadIdx.x;
    int nnz = g_nnz[i];
    for (int e = tid; e < nnz; e += 128) {
        ec[e] = g_cols[i * MAXW + e];
        ev[e] = g_vals[i * MAXW + e];
    }
    __syncthreads();
    if (tid < T_STEPS * IN_DIM) {
        float a0 = 0.f, a1 = 0.f, a2 = 0.f, a3 = 0.f;
        int e = 0;
        for (; e + 4 <= nnz; e += 4) {
            a0 += ev[e]     * g_xT[(size_t)ec[e]     * 96 + tid];
            a1 += ev[e + 1] * g_xT[(size_t)ec[e + 1] * 96 + tid];
            a2 += ev[e + 2] * g_xT[(size_t)ec[e + 2] * 96 + tid];
            a3 += ev[e + 3] * g_xT[(size_t)ec[e + 3] * 96 + tid];
        }
        for (; e < nnz; e++) a0 += ev[e] * g_xT[(size_t)ec[e] * 96 + tid];
        int t = tid >> 1, k = tid & 1;
        g_AX[(size_t)t * (N_NODES * IN_DIM) + i * IN_DIM + k] = (a0 + a1) + (a2 + a3);
    }
}

__global__ void init_state() {
    int idx = blockIdx.x * blockDim.x + threadIdx.x;
    if (idx < N_NODES * H_DIM) {
        g_h0[0][idx] = 0.f; g_h0[1][idx] = 0.f;
        g_h1[0][idx] = 0.f; g_h1[1][idx] = 0.f;
    }
    if (idx == 0) { g_cnt = 0u; g_gen = 0u; }
}

// ---------------- fused GEMM + gates (32 rows, 512 threads) ----------------
// comb = az@Wg + z@Wl + b ; gates ; update c (smem) and h (smem transposed + global)
template <int K>
__device__ __forceinline__ void cell_gemm(
    const float* azb, const float* zb,
    const float* __restrict__ Wg, const float* __restrict__ Wl,
    const float* __restrict__ bias,
    float* s_comb, float* s_cL, float* hT, float* __restrict__ hG,
    int row0, int tid) {
    int q  = tid >> 7;        // row quarter: rows 8q..8q+7
    int t  = tid & 127;
    int c0 = t, c1 = t + 128;

    ull accA[4], accB[4];
    const ull zz = pack2(0.f, 0.f);
    #pragma unroll
    for (int rp = 0; rp < 4; rp++) { accA[rp] = zz; accB[rp] = zz; }

    #pragma unroll 2
    for (int k = 0; k < K; k++) {
        float wgA = __ldg(&Wg[k * H4 + c0]);
        float wgB = __ldg(&Wg[k * H4 + c1]);
        float wlA = __ldg(&Wl[k * H4 + c0]);
        float wlB = __ldg(&Wl[k * H4 + c1]);
        ull wgAp = pack2(wgA, wgA), wgBp = pack2(wgB, wgB);
        ull wlAp = pack2(wlA, wlA), wlBp = pack2(wlB, wlB);
        const ull* a2 = reinterpret_cast<const ull*>(azb + k * SR) + 4 * q;
        const ull* b2 = reinterpret_cast<const ull*>(zb  + k * SR) + 4 * q;
        #pragma unroll
        for (int rp = 0; rp < 4; rp++) {
            ull av = a2[rp];
            fma2(accA[rp], av, wgAp);
            fma2(accB[rp], av, wgBp);
        }
        #pragma unroll
        for (int rp = 0; rp < 4; rp++) {
            ull bv = b2[rp];
            fma2(accA[rp], bv, wlAp);
            fma2(accB[rp], bv, wlBp);
        }
    }

    float bA = bias[c0], bB = bias[c1];
    #pragma unroll
    for (int rp = 0; rp < 4; rp++) {
        int r = 8 * q + 2 * rp;
        float lo, hi;
        unpack2(accA[rp], lo, hi);
        s_comb[r * H4 + c0]       = lo + bA;
        s_comb[(r + 1) * H4 + c0] = hi + bA;
        unpack2(accB[rp], lo, hi);
        s_comb[r * H4 + c1]       = lo + bB;
        s_comb[(r + 1) * H4 + c1] = hi + bB;
    }
    __syncthreads();

    for (int u = tid; u < 32 * H_DIM; u += 512) {
        int r = u >> 6, hc = u & 63;
        const float* cb = s_comb + r * H4;
        float ig = cb[hc];
        float fg = cb[64 + hc];
        float og = cb[128 + hc];
        float gg = cb[192 + hc];
        float cold = s_cL[u];
        float nc = sigmoidf_(fg) * cold + sigmoidf_(ig) * tanhf(gg);
        float nh = sigmoidf_(og) * tanhf(nc);
        s_cL[u] = nc;
        hT[hc * SR + r] = nh;
        hG[(size_t)(row0 + r) * H_DIM + hc] = nh;
    }
}

// ---------------- persistent kernel ----------------
// smem floats:
//  AZB  [0, 4420)       130 x SR : rows0-1 AX, 2-65 A@h0, 66-129 A@h1
//  ZB   [4420, 8840)    130 x SR : rows0-1 x_t, 2-65 h0T, 66-129 h1T
//  COMB [8840, 17032)   32 x 256
//  CST  [17032, 21128)  2 x 32 x 64
//  ECOL [21128, 26248)  32 x MAXW int
//  EVAL [26248, 31368)  32 x MAXW
//  NNZ  [31368, 31400)  32 int
#define SMEM_FLOATS 31400
#define SMEM_BYTES  (SMEM_FLOATS * 4)

__global__ void __launch_bounds__(512, 1) persist_kernel(
    const float* __restrict__ x,
    const float* __restrict__ outW,
    const float* __restrict__ outb,
    float* __restrict__ out) {
    extern __shared__ __align__(16) float sm[];
    float* s_azb  = sm;
    float* s_zb   = sm + 4420;
    float* s_comb = sm + 8840;
    float* s_c    = sm + 17032;
    int*   s_ecol = (int*)(sm + 21128);
    float* s_eval = sm + 26248;
    int*   s_nnz  = (int*)(sm + 31368);

    int tid = threadIdx.x;
    int w = tid >> 5, lane = tid & 31;
    int bid = blockIdx.x;

    if (bid >= NBW) {               // spinner blocks: just keep the barrier honest
        for (int s = 0; s < T_STEPS; s++) gridbar();
        return;
    }
    int row0 = bid * 32;

    // one-time init: zero az/z/c, stage edges + nnz
    for (int u = tid; u < 4420; u += 512) { s_azb[u] = 0.f; s_zb[u] = 0.f; }
    for (int u = tid; u < 4096; u += 512) s_c[u] = 0.f;
    for (int u = tid; u < 32 * MAXW; u += 512) {
        int r = u / MAXW, e = u - r * MAXW;
        s_ecol[u] = g_cols[(row0 + r) * MAXW + e];
        s_eval[u] = g_vals[(row0 + r) * MAXW + e];
    }
    if (tid < 32) s_nnz[tid] = g_nnz[row0 + tid];
    __syncthreads();

    for (int t = 0; t < T_STEPS; t++) {
        int pc = t & 1, p1 = pc ^ 1;
        const float* x_t = x + (size_t)t * N_NODES * IN_DIM;

        // ---- phase 1: stage x_t/AX, cell0 (no gathers!) ----
        for (int u = tid; u < 64; u += 512) {
            int r = u >> 1, k = u & 1;
            s_zb[k * SR + r]  = x_t[(row0 + r) * IN_DIM + k];
            s_azb[k * SR + r] = g_AX[(size_t)t * (N_NODES * IN_DIM) + (row0 + r) * IN_DIM + k];
        }
        __syncthreads();
        cell_gemm<66>(s_azb, s_zb, g_Wg0, g_Wl0, g_b0,
                      s_comb, s_c, s_zb + 2 * SR, g_h0[p1], row0, tid);

        gridbar();   // all blocks' h0n visible; h1c from t-1 also safe

        // ---- phase 2: single gather pass (h0n + h1c), then cell1 ----
        {
            const float* h0s = g_h0[p1];
            const float* h1s = g_h1[pc];
            for (int rr = 0; rr < 2; rr++) {
                int r = 2 * w + rr;
                int nnz = s_nnz[r];
                const int*   ec = s_ecol + r * MAXW;
                const float* ev = s_eval + r * MAXW;
                float a0 = 0.f, a1 = 0.f, b0 = 0.f, b1 = 0.f;
                int e = 0;
                for (; e + 8 <= nnz; e += 8) {
                    float2 hv[8], gv[8]; float vv[8];
                    #pragma unroll
                    for (int u2 = 0; u2 < 8; u2++) {
                        int j = ec[e + u2];
                        vv[u2] = ev[e + u2];
                        hv[u2] = __ldg(reinterpret_cast<const float2*>(
                                     h0s + (size_t)j * H_DIM) + lane);
                        gv[u2] = __ldg(reinterpret_cast<const float2*>(
                                     h1s + (size_t)j * H_DIM) + lane);
                    }
                    #pragma unroll
                    for (int u2 = 0; u2 < 8; u2++) {
                        a0 += vv[u2] * hv[u2].x; a1 += vv[u2] * hv[u2].y;
                        b0 += vv[u2] * gv[u2].x; b1 += vv[u2] * gv[u2].y;
                    }
                }
                for (; e < nnz; e++) {
                    int j = ec[e]; float v = ev[e];
                    float2 hv = __ldg(reinterpret_cast<const float2*>(
                                    h0s + (size_t)j * H_DIM) + lane);
                    float2 gv = __ldg(reinterpret_cast<const float2*>(
                                    h1s + (size_t)j * H_DIM) + lane);
                    a0 += v * hv.x; a1 += v * hv.y;
                    b0 += v * gv.x; b1 += v * gv.y;
                }
                // A@h0n -> rows 2..65 (feeds cell1 now AND next step's cell0)
                s_azb[(2 + 2 * lane) * SR + r]  = a0;
                s_azb[(3 + 2 * lane) * SR + r]  = a1;
                // A@h1c -> rows 66..129
                s_azb[(66 + 2 * lane) * SR + r] = b0;
                s_azb[(67 + 2 * lane) * SR + r] = b1;
            }
        }
        __syncthreads();
        cell_gemm<128>(s_azb + 2 * SR, s_zb + 2 * SR, g_Wg1, g_Wl1, g_b1,
                       s_comb, s_c + 2048, s_zb + 66 * SR, g_h1[p1], row0, tid);
        // no end-of-step barrier needed (double-buffer parity analysis)
    }
    __syncthreads();

    // ---- output: out = h1 @ outW + outb, h1 read from smem h1T ----
    for (int u = tid; u < 32 * P_DIM; u += 512) {
        int r = u / P_DIM, p = u - r * P_DIM;
        float acc = outb[p];
        #pragma unroll
        for (int c2 = 0; c2 < H_DIM; c2++)
            acc += s_zb[(66 + c2) * SR + r] * __ldg(&outW[c2 * P_DIM + p]);
        out[(size_t)(row0 + r) * P_DIM + p] = acc;
    }
}

// ---------------- launch ----------------
extern "C" void kernel_launch(void* const* d_in, const int* in_sizes, int n_in,
                              void* d_out, int out_size) {
    const float* x     = (const float*)d_in[0];
    const float* adj   = (const float*)d_in[1];
    const float* gcWi0 = (const float*)d_in[2];
    const float* gcbi0 = (const float*)d_in[3];
    const float* gcWh0 = (const float*)d_in[4];
    const float* gcbh0 = (const float*)d_in[5];
    const float* liWi0 = (const float*)d_in[6];
    const float* libi0 = (const float*)d_in[7];
    const float* liWh0 = (const float*)d_in[8];
    const float* libh0 = (const float*)d_in[9];
    const float* gcWi1 = (const float*)d_in[10];
    const float* gcbi1 = (const float*)d_in[11];
    const float* gcWh1 = (const float*)d_in[12];
    const float* gcbh1 = (const float*)d_in[13];
    const float* liWi1 = (const float*)d_in[14];
    const float* libi1 = (const float*)d_in[15];
    const float* liWh1 = (const float*)d_in[16];
    const float* libh1 = (const float*)d_in[17];
    const float* outW  = (const float*)d_in[18];
    const float* outb  = (const float*)d_in[19];

    static int smem_set = 0;
    if (!smem_set) {
        cudaFuncSetAttribute(persist_kernel,
                             cudaFuncAttributeMaxDynamicSharedMemorySize,
                             SMEM_BYTES);
        smem_set = 1;
    }

    rowsum_kernel<<<N_NODES, 256>>>(adj);
    build_sparse<<<N_NODES, 256>>>(adj);
    prep_weights<<<1, 256>>>(gcWi0, gcbi0, gcWh0, gcbh0, liWi0, libi0, liWh0, libh0,
                             gcWi1, gcbi1, gcWh1, gcbh1, liWi1, libi1, liWh1, libh1);
    xpose_kernel<<<(T_STEPS * N_NODES * IN_DIM + 255) / 256, 256>>>(x);
    ax_kernel<<<N_NODES, 128>>>();
    init_state<<<(N_NODES * H_DIM + 255) / 256, 256>>>();
    persist_kernel<<<NBT, 512, SMEM_BYTES>>>(x, outW, outb, (float*)d_out);
}